// round 2
// baseline (speedup 1.0000x reference)
#include <cuda_runtime.h>
#include <cuda_bf16.h>
#include <mma.h>
#include <math.h>

using namespace nvcuda;

// Problem constants
constexpr int B_ = 8;
constexpr int T_ = 2048;
constexpr int C_ = 1024;
constexpr int M_ROWS = B_ * T_;      // 16384
constexpr int N_QKV  = 3 * C_;       // 3072

// GEMM tiling
constexpr int BM = 128;
constexpr int BN = 128;
constexpr int BK = 16;
constexpr int A_STRIDE = BK + 4;     // 20 floats (80B rows, 16B aligned)
constexpr int B_NT_STRIDE = BN + 4;  // 132 floats
constexpr int BS_BUF = 2560;         // max(128*20, 16*132) rounded up

// Scratch (device globals: allocation-free per harness rules)
__device__ float g_qkv[(size_t)M_ROWS * N_QKV];   // [B*T, 3C]
__device__ float g_S[(size_t)B_ * T_ * T_];       // [B, T, T]
__device__ float g_O[(size_t)M_ROWS * C_];        // [B*T, C]

__device__ __forceinline__ unsigned smem_u32(const void* p) {
    return (unsigned)__cvta_generic_to_shared(p);
}
__device__ __forceinline__ void cp16(unsigned s, const void* g) {
    asm volatile("cp.async.ca.shared.global [%0], [%1], 16;\n" :: "r"(s), "l"(g));
}
__device__ __forceinline__ void cp_commit() {
    asm volatile("cp.async.commit_group;\n" ::: "memory");
}
template <int N>
__device__ __forceinline__ void cp_wait() {
    asm volatile("cp.async.wait_group %0;\n" :: "n"(N) : "memory");
}

// ---------------------------------------------------------------------------
// tf32 WMMA GEMM, 128x128 CTA tile, cp.async double-buffered.
// C = alpha * A @ B (TRANS_B=0, B is [K,N]) or alpha * A @ B^T (TRANS_B=1,
// B is [N,K]).
// CAUSAL: 0 none; 1 skip blocks strictly above diagonal (score GEMM);
//         2 limit K-loop to m0+BM (P@V GEMM; A cols beyond row are zero).
// ---------------------------------------------------------------------------
template <bool TRANS_B, int CAUSAL>
__global__ void __launch_bounds__(256, 1)
gemm_tf32_kernel(const float* __restrict__ Ag, const float* __restrict__ Bg,
                 float* __restrict__ Cg,
                 int M, int N, int K, int lda, int ldb, int ldc,
                 long long sA, long long sB, long long sC, float alpha)
{
    const long long bz = blockIdx.z;
    const float* A  = Ag + bz * sA;
    const float* Bp = Bg + bz * sB;
    float*       Cp = Cg + bz * sC;

    const int m0 = blockIdx.y * BM;
    const int n0 = blockIdx.x * BN;

    if (CAUSAL == 1 && n0 > m0 + BM - 1) return;   // fully above diagonal
    int kend = K;
    if (CAUSAL == 2) kend = min(K, m0 + BM);       // rest of A-row is zero
    const int ntiles = kend / BK;

    __shared__ float As[2][BM][A_STRIDE];
    __shared__ float Bs[2][BS_BUF];

    const int tid  = threadIdx.x;
    const int warp = tid >> 5;
    const int wm   = (warp >> 2) * 64;   // 2 warp-rows
    const int wn   = (warp & 3) * 32;    // 4 warp-cols

    wmma::fragment<wmma::accumulator, 16, 16, 8, float> acc[4][2];
    #pragma unroll
    for (int i = 0; i < 4; i++)
        #pragma unroll
        for (int j = 0; j < 2; j++)
            wmma::fill_fragment(acc[i][j], 0.0f);

    // ---- async stage loader: tile kt -> buffer b ----
    auto stage = [&](int kt, int b) {
        const int kbase = kt * BK;
        // A tile 128x16: 512 x 16B chunks
        #pragma unroll
        for (int i = tid; i < (BM * BK) / 4; i += 256) {
            int r = i >> 2, c = (i & 3) * 4;
            cp16(smem_u32(&As[b][r][c]),
                 &A[(size_t)(m0 + r) * lda + kbase + c]);
        }
        if constexpr (TRANS_B) {
            // B tile 128x16 from [N,K]
            #pragma unroll
            for (int i = tid; i < (BN * BK) / 4; i += 256) {
                int r = i >> 2, c = (i & 3) * 4;
                cp16(smem_u32(&Bs[b][r * A_STRIDE + c]),
                     &Bp[(size_t)(n0 + r) * ldb + kbase + c]);
            }
        } else {
            // B tile 16x128 from [K,N]
            #pragma unroll
            for (int i = tid; i < (BK * BN) / 4; i += 256) {
                int r = i >> 5, c = (i & 31) * 4;
                cp16(smem_u32(&Bs[b][r * B_NT_STRIDE + c]),
                     &Bp[(size_t)(kbase + r) * ldb + n0 + c]);
            }
        }
    };

    stage(0, 0);
    cp_commit();

    for (int kt = 0; kt < ntiles; kt++) {
        const int buf = kt & 1;
        if (kt + 1 < ntiles) {
            stage(kt + 1, (kt + 1) & 1);
            cp_commit();
            cp_wait<1>();
        } else {
            cp_wait<0>();
        }
        __syncthreads();

        #pragma unroll
        for (int kk = 0; kk < BK; kk += 8) {
            wmma::fragment<wmma::matrix_a, 16, 16, 8,
                           wmma::precision::tf32, wmma::row_major> af[4];
            #pragma unroll
            for (int im = 0; im < 4; im++) {
                wmma::load_matrix_sync(af[im], &As[buf][wm + im * 16][kk],
                                       A_STRIDE);
                #pragma unroll
                for (int t = 0; t < af[im].num_elements; t++)
                    af[im].x[t] = wmma::__float_to_tf32(af[im].x[t]);
            }
            if constexpr (TRANS_B) {
                wmma::fragment<wmma::matrix_b, 16, 16, 8,
                               wmma::precision::tf32, wmma::col_major> bf[2];
                #pragma unroll
                for (int in = 0; in < 2; in++) {
                    wmma::load_matrix_sync(
                        bf[in], &Bs[buf][(wn + in * 16) * A_STRIDE + kk],
                        A_STRIDE);
                    #pragma unroll
                    for (int t = 0; t < bf[in].num_elements; t++)
                        bf[in].x[t] = wmma::__float_to_tf32(bf[in].x[t]);
                }
                #pragma unroll
                for (int im = 0; im < 4; im++)
                    #pragma unroll
                    for (int in = 0; in < 2; in++)
                        wmma::mma_sync(acc[im][in], af[im], bf[in], acc[im][in]);
            } else {
                wmma::fragment<wmma::matrix_b, 16, 16, 8,
                               wmma::precision::tf32, wmma::row_major> bf[2];
                #pragma unroll
                for (int in = 0; in < 2; in++) {
                    wmma::load_matrix_sync(
                        bf[in], &Bs[buf][kk * B_NT_STRIDE + wn + in * 16],
                        B_NT_STRIDE);
                    #pragma unroll
                    for (int t = 0; t < bf[in].num_elements; t++)
                        bf[in].x[t] = wmma::__float_to_tf32(bf[in].x[t]);
                }
                #pragma unroll
                for (int im = 0; im < 4; im++)
                    #pragma unroll
                    for (int in = 0; in < 2; in++)
                        wmma::mma_sync(acc[im][in], af[im], bf[in], acc[im][in]);
            }
        }
        __syncthreads();
    }

    #pragma unroll
    for (int im = 0; im < 4; im++)
        #pragma unroll
        for (int in = 0; in < 2; in++) {
            #pragma unroll
            for (int t = 0; t < acc[im][in].num_elements; t++)
                acc[im][in].x[t] *= alpha;
            wmma::store_matrix_sync(
                &Cp[(size_t)(m0 + wm + im * 16) * ldc + n0 + wn + in * 16],
                acc[im][in], ldc, wmma::mem_row_major);
        }
}

// ---------------------------------------------------------------------------
// Causal row softmax over S[B,T,T]: row i uses cols [0,i]; cols > i set to 0.
// ---------------------------------------------------------------------------
__device__ __forceinline__ float blockReduce(float v, bool is_max)
{
    __shared__ float sh[33];
    __syncthreads();
    int lane = threadIdx.x & 31, wid = threadIdx.x >> 5;
    #pragma unroll
    for (int o = 16; o; o >>= 1) {
        float u = __shfl_xor_sync(0xFFFFFFFFu, v, o);
        v = is_max ? fmaxf(v, u) : (v + u);
    }
    if (lane == 0) sh[wid] = v;
    __syncthreads();
    if (wid == 0) {
        v = (lane < (blockDim.x >> 5)) ? sh[lane] : (is_max ? -INFINITY : 0.0f);
        #pragma unroll
        for (int o = 16; o; o >>= 1) {
            float u = __shfl_xor_sync(0xFFFFFFFFu, v, o);
            v = is_max ? fmaxf(v, u) : (v + u);
        }
        if (lane == 0) sh[32] = v;
    }
    __syncthreads();
    return sh[32];
}

__global__ void __launch_bounds__(256)
softmax_causal_kernel(float* __restrict__ S)
{
    const int row = blockIdx.x;
    const int i   = row % T_;
    float* Srow = S + (size_t)row * T_;
    const int n = i + 1;

    float m = -INFINITY;
    for (int j = threadIdx.x; j < n; j += blockDim.x)
        m = fmaxf(m, Srow[j]);
    m = blockReduce(m, true);

    float s = 0.0f;
    for (int j = threadIdx.x; j < n; j += blockDim.x) {
        float e = __expf(Srow[j] - m);
        Srow[j] = e;
        s += e;
    }
    s = blockReduce(s, false);
    const float inv = 1.0f / s;

    for (int j = threadIdx.x; j < n; j += blockDim.x)
        Srow[j] *= inv;
    for (int j = n + threadIdx.x; j < T_; j += blockDim.x)
        Srow[j] = 0.0f;
}

// ---------------------------------------------------------------------------
// Launch
// ---------------------------------------------------------------------------
extern "C" void kernel_launch(void* const* d_in, const int* in_sizes, int n_in,
                              void* d_out, int out_size)
{
    const float* x     = (const float*)d_in[0];   // [B, T, C]
    const float* Wqkv  = (const float*)d_in[1];   // [C, 3C]
    const float* Wproj = (const float*)d_in[2];   // [C, C]
    float* out = (float*)d_out;                   // [B, T, C]

    static float* qkv = nullptr;
    static float* S   = nullptr;
    static float* O   = nullptr;
    if (!qkv) {
        cudaGetSymbolAddress((void**)&qkv, g_qkv);
        cudaGetSymbolAddress((void**)&S,   g_S);
        cudaGetSymbolAddress((void**)&O,   g_O);
    }

    const float scale = 1.0f / 32.0f;   // C^-0.5, C=1024
    dim3 blk(256);

    // 1. qkv = x @ Wqkv : [16384,1024] @ [1024,3072]
    {
        dim3 grid(N_QKV / BN, M_ROWS / BM, 1);
        gemm_tf32_kernel<false, 0><<<grid, blk>>>(
            x, Wqkv, qkv, M_ROWS, N_QKV, C_, C_, N_QKV, N_QKV,
            0, 0, 0, 1.0f);
    }

    // 2. S_b = Q_b @ K_b^T * scale (batched, causal block skip)
    {
        dim3 grid(T_ / BN, T_ / BM, B_);
        gemm_tf32_kernel<true, 1><<<grid, blk>>>(
            qkv /*Q*/, qkv + C_ /*K*/, S,
            T_, T_, C_, N_QKV, N_QKV, T_,
            (long long)T_ * N_QKV, (long long)T_ * N_QKV, (long long)T_ * T_,
            scale);
    }

    // 3. causal softmax rows of S
    softmax_causal_kernel<<<M_ROWS, 256>>>(S);

    // 4. O_b = P_b @ V_b (batched, K-loop limited to diagonal)
    {
        dim3 grid(C_ / BN, T_ / BM, B_);
        gemm_tf32_kernel<false, 2><<<grid, blk>>>(
            S, qkv + 2 * C_ /*V*/, O,
            T_, C_, T_, T_, N_QKV, C_,
            (long long)T_ * T_, (long long)T_ * N_QKV, (long long)T_ * C_,
            1.0f);
    }

    // 5. out = O @ Wproj : [16384,1024] @ [1024,1024]
    {
        dim3 grid(C_ / BN, M_ROWS / BM, 1);
        gemm_tf32_kernel<false, 0><<<grid, blk>>>(
            O, Wproj, out, M_ROWS, C_, C_, C_, C_, C_,
            0, 0, 0, 1.0f);
    }
}

// round 3
// speedup vs baseline: 1.1693x; 1.1693x over previous
#include <cuda_runtime.h>
#include <cuda_bf16.h>
#include <mma.h>
#include <math.h>

using namespace nvcuda;

// Problem constants
constexpr int B_ = 8;
constexpr int T_ = 2048;
constexpr int C_ = 1024;
constexpr int M_ROWS = B_ * T_;      // 16384
constexpr int N_QKV  = 3 * C_;       // 3072

// GEMM tiling
constexpr int BM = 64;
constexpr int BN = 64;
constexpr int BK = 32;
constexpr int AS_STRIDE = BK + 4;    // 36 floats
constexpr int BN_STRIDE = BN + 4;    // 68 floats
constexpr int BS_BUF = 2304;         // max(64*36, 32*68)=2304/2176

// Scratch (device globals: allocation-free per harness rules)
__device__ float g_x[(size_t)M_ROWS * C_];        // tf32-rounded x
__device__ float g_wq[(size_t)C_ * N_QKV];        // tf32-rounded Wqkv
__device__ float g_wp[(size_t)C_ * C_];           // tf32-rounded Wproj
__device__ float g_qkv[(size_t)M_ROWS * N_QKV];   // [B*T, 3C] (tf32-rounded)
__device__ float g_S[(size_t)B_ * T_ * T_];       // [B, T, T]
__device__ float g_O[(size_t)M_ROWS * C_];        // [B*T, C] (tf32-rounded)

__device__ __forceinline__ unsigned smem_u32(const void* p) {
    return (unsigned)__cvta_generic_to_shared(p);
}
__device__ __forceinline__ void cp16(unsigned s, const void* g) {
    asm volatile("cp.async.ca.shared.global [%0], [%1], 16;\n" :: "r"(s), "l"(g));
}
__device__ __forceinline__ void cp_commit() {
    asm volatile("cp.async.commit_group;\n" ::: "memory");
}
template <int N>
__device__ __forceinline__ void cp_wait() {
    asm volatile("cp.async.wait_group %0;\n" :: "n"(N) : "memory");
}

// ---------------------------------------------------------------------------
// Elementwise tf32 rounding of a buffer (float4-vectorized).
// ---------------------------------------------------------------------------
__global__ void __launch_bounds__(256)
round_tf32_kernel(const float* __restrict__ in, float* __restrict__ out, int n4)
{
    int i = blockIdx.x * blockDim.x + threadIdx.x;
    if (i >= n4) return;
    float4 v = ((const float4*)in)[i];
    v.x = wmma::__float_to_tf32(v.x);
    v.y = wmma::__float_to_tf32(v.y);
    v.z = wmma::__float_to_tf32(v.z);
    v.w = wmma::__float_to_tf32(v.w);
    ((float4*)out)[i] = v;
}

// ---------------------------------------------------------------------------
// tf32 WMMA GEMM, 64x64x32 tile, 128 threads, cp.async double-buffered.
// ALL operands must already be tf32-rounded in global memory -> no cvt here.
// C = alpha * A @ B (TRANS_B=0, B is [K,N]) or A @ B^T (TRANS_B=1, B [N,K]).
// CAUSAL: 0 none; 1 skip blocks above diagonal; 2 limit K-loop to m0+BM.
// ROUND_OUT: round epilogue store to tf32 (when C feeds a later GEMM).
// ---------------------------------------------------------------------------
template <bool TRANS_B, int CAUSAL, bool ROUND_OUT>
__global__ void __launch_bounds__(128)
gemm_tf32_kernel(const float* __restrict__ Ag, const float* __restrict__ Bg,
                 float* __restrict__ Cg,
                 int M, int N, int K, int lda, int ldb, int ldc,
                 long long sA, long long sB, long long sC, float alpha)
{
    const long long bz = blockIdx.z;
    const float* A  = Ag + bz * sA;
    const float* Bp = Bg + bz * sB;
    float*       Cp = Cg + bz * sC;

    const int m0 = blockIdx.y * BM;
    const int n0 = blockIdx.x * BN;

    if (CAUSAL == 1 && n0 > m0 + BM - 1) return;
    int kend = K;
    if (CAUSAL == 2) kend = min(K, m0 + BM);
    const int ntiles = kend / BK;

    __shared__ float As[2][BM][AS_STRIDE];
    __shared__ float Bs[2][BS_BUF];

    const int tid  = threadIdx.x;
    const int warp = tid >> 5;
    const int wm   = (warp >> 1) * 32;
    const int wn   = (warp & 1) * 32;

    wmma::fragment<wmma::accumulator, 16, 16, 8, float> acc[2][2];
    #pragma unroll
    for (int i = 0; i < 2; i++)
        #pragma unroll
        for (int j = 0; j < 2; j++)
            wmma::fill_fragment(acc[i][j], 0.0f);

    auto stage = [&](int kt, int b) {
        const int kbase = kt * BK;
        // A tile 64x32: 512 16B-chunks, 4 per thread
        #pragma unroll
        for (int i = tid; i < (BM * BK) / 4; i += 128) {
            int r = i >> 3, c = (i & 7) * 4;
            cp16(smem_u32(&As[b][r][c]),
                 &A[(size_t)(m0 + r) * lda + kbase + c]);
        }
        if constexpr (TRANS_B) {
            #pragma unroll
            for (int i = tid; i < (BN * BK) / 4; i += 128) {
                int r = i >> 3, c = (i & 7) * 4;
                cp16(smem_u32(&Bs[b][r * AS_STRIDE + c]),
                     &Bp[(size_t)(n0 + r) * ldb + kbase + c]);
            }
        } else {
            #pragma unroll
            for (int i = tid; i < (BK * BN) / 4; i += 128) {
                int r = i >> 4, c = (i & 15) * 4;
                cp16(smem_u32(&Bs[b][r * BN_STRIDE + c]),
                     &Bp[(size_t)(kbase + r) * ldb + n0 + c]);
            }
        }
    };

    stage(0, 0);
    cp_commit();

    for (int kt = 0; kt < ntiles; kt++) {
        const int buf = kt & 1;
        if (kt + 1 < ntiles) {
            stage(kt + 1, (kt + 1) & 1);
            cp_commit();
            cp_wait<1>();
        } else {
            cp_wait<0>();
        }
        __syncthreads();

        #pragma unroll
        for (int kk = 0; kk < BK; kk += 8) {
            wmma::fragment<wmma::matrix_a, 16, 16, 8,
                           wmma::precision::tf32, wmma::row_major> af[2];
            #pragma unroll
            for (int im = 0; im < 2; im++)
                wmma::load_matrix_sync(af[im], &As[buf][wm + im * 16][kk],
                                       AS_STRIDE);
            if constexpr (TRANS_B) {
                wmma::fragment<wmma::matrix_b, 16, 16, 8,
                               wmma::precision::tf32, wmma::col_major> bf[2];
                #pragma unroll
                for (int in = 0; in < 2; in++)
                    wmma::load_matrix_sync(
                        bf[in], &Bs[buf][(wn + in * 16) * AS_STRIDE + kk],
                        AS_STRIDE);
                #pragma unroll
                for (int im = 0; im < 2; im++)
                    #pragma unroll
                    for (int in = 0; in < 2; in++)
                        wmma::mma_sync(acc[im][in], af[im], bf[in], acc[im][in]);
            } else {
                wmma::fragment<wmma::matrix_b, 16, 16, 8,
                               wmma::precision::tf32, wmma::row_major> bf[2];
                #pragma unroll
                for (int in = 0; in < 2; in++)
                    wmma::load_matrix_sync(
                        bf[in], &Bs[buf][kk * BN_STRIDE + wn + in * 16],
                        BN_STRIDE);
                #pragma unroll
                for (int im = 0; im < 2; im++)
                    #pragma unroll
                    for (int in = 0; in < 2; in++)
                        wmma::mma_sync(acc[im][in], af[im], bf[in], acc[im][in]);
            }
        }
        __syncthreads();
    }

    #pragma unroll
    for (int im = 0; im < 2; im++)
        #pragma unroll
        for (int in = 0; in < 2; in++) {
            #pragma unroll
            for (int t = 0; t < acc[im][in].num_elements; t++) {
                float v = acc[im][in].x[t] * alpha;
                if (ROUND_OUT) v = wmma::__float_to_tf32(v);
                acc[im][in].x[t] = v;
            }
            wmma::store_matrix_sync(
                &Cp[(size_t)(m0 + wm + im * 16) * ldc + n0 + wn + in * 16],
                acc[im][in], ldc, wmma::mem_row_major);
        }
}

// ---------------------------------------------------------------------------
// Causal row softmax; output rounded to tf32 (feeds P@V GEMM).
// ---------------------------------------------------------------------------
__device__ __forceinline__ float blockReduce(float v, bool is_max)
{
    __shared__ float sh[33];
    __syncthreads();
    int lane = threadIdx.x & 31, wid = threadIdx.x >> 5;
    #pragma unroll
    for (int o = 16; o; o >>= 1) {
        float u = __shfl_xor_sync(0xFFFFFFFFu, v, o);
        v = is_max ? fmaxf(v, u) : (v + u);
    }
    if (lane == 0) sh[wid] = v;
    __syncthreads();
    if (wid == 0) {
        v = (lane < (blockDim.x >> 5)) ? sh[lane] : (is_max ? -INFINITY : 0.0f);
        #pragma unroll
        for (int o = 16; o; o >>= 1) {
            float u = __shfl_xor_sync(0xFFFFFFFFu, v, o);
            v = is_max ? fmaxf(v, u) : (v + u);
        }
        if (lane == 0) sh[32] = v;
    }
    __syncthreads();
    return sh[32];
}

__global__ void __launch_bounds__(256)
softmax_causal_kernel(float* __restrict__ S)
{
    const int row = blockIdx.x;
    const int i   = row % T_;
    float* Srow = S + (size_t)row * T_;
    const int n = i + 1;

    float m = -INFINITY;
    for (int j = threadIdx.x; j < n; j += blockDim.x)
        m = fmaxf(m, Srow[j]);
    m = blockReduce(m, true);

    float s = 0.0f;
    for (int j = threadIdx.x; j < n; j += blockDim.x) {
        float e = __expf(Srow[j] - m);
        Srow[j] = e;
        s += e;
    }
    s = blockReduce(s, false);
    const float inv = 1.0f / s;

    for (int j = threadIdx.x; j < n; j += blockDim.x)
        Srow[j] = wmma::__float_to_tf32(Srow[j] * inv);
    for (int j = n + threadIdx.x; j < T_; j += blockDim.x)
        Srow[j] = 0.0f;
}

// ---------------------------------------------------------------------------
// Launch
// ---------------------------------------------------------------------------
extern "C" void kernel_launch(void* const* d_in, const int* in_sizes, int n_in,
                              void* d_out, int out_size)
{
    const float* x     = (const float*)d_in[0];   // [B, T, C]
    const float* Wqkv  = (const float*)d_in[1];   // [C, 3C]
    const float* Wproj = (const float*)d_in[2];   // [C, C]
    float* out = (float*)d_out;                   // [B, T, C]

    static float *xr = nullptr, *wq = nullptr, *wp = nullptr;
    static float *qkv = nullptr, *S = nullptr, *O = nullptr;
    if (!qkv) {
        cudaGetSymbolAddress((void**)&xr,  g_x);
        cudaGetSymbolAddress((void**)&wq,  g_wq);
        cudaGetSymbolAddress((void**)&wp,  g_wp);
        cudaGetSymbolAddress((void**)&qkv, g_qkv);
        cudaGetSymbolAddress((void**)&S,   g_S);
        cudaGetSymbolAddress((void**)&O,   g_O);
    }

    const float scale = 1.0f / 32.0f;   // C^-0.5, C=1024
    dim3 blk(128);

    // 0. pre-round operands to tf32
    {
        int n4x = (M_ROWS * C_) / 4;
        round_tf32_kernel<<<(n4x + 255) / 256, 256>>>(x, xr, n4x);
        int n4q = (C_ * N_QKV) / 4;
        round_tf32_kernel<<<(n4q + 255) / 256, 256>>>(Wqkv, wq, n4q);
        int n4p = (C_ * C_) / 4;
        round_tf32_kernel<<<(n4p + 255) / 256, 256>>>(Wproj, wp, n4p);
    }

    // 1. qkv = x @ Wqkv (round output: feeds QK^T and P@V)
    {
        dim3 grid(N_QKV / BN, M_ROWS / BM, 1);
        gemm_tf32_kernel<false, 0, true><<<grid, blk>>>(
            xr, wq, qkv, M_ROWS, N_QKV, C_, C_, N_QKV, N_QKV,
            0, 0, 0, 1.0f);
    }

    // 2. S_b = Q_b @ K_b^T * scale (causal block skip; keep fp32 for softmax)
    {
        dim3 grid(T_ / BN, T_ / BM, B_);
        gemm_tf32_kernel<true, 1, false><<<grid, blk>>>(
            qkv, qkv + C_, S,
            T_, T_, C_, N_QKV, N_QKV, T_,
            (long long)T_ * N_QKV, (long long)T_ * N_QKV, (long long)T_ * T_,
            scale);
    }

    // 3. causal softmax (rounds P to tf32)
    softmax_causal_kernel<<<M_ROWS, 256>>>(S);

    // 4. O_b = P_b @ V_b (K-loop limited; round output for proj GEMM)
    {
        dim3 grid(C_ / BN, T_ / BM, B_);
        gemm_tf32_kernel<false, 2, true><<<grid, blk>>>(
            S, qkv + 2 * C_, O,
            T_, C_, T_, T_, N_QKV, C_,
            (long long)T_ * T_, (long long)T_ * N_QKV, (long long)T_ * C_,
            1.0f);
    }

    // 5. out = O @ Wproj (final: full fp32 store)
    {
        dim3 grid(C_ / BN, M_ROWS / BM, 1);
        gemm_tf32_kernel<false, 0, false><<<grid, blk>>>(
            O, wp, out, M_ROWS, C_, C_, C_, C_, C_,
            0, 0, 0, 1.0f);
    }
}